// round 11
// baseline (speedup 1.0000x reference)
#include <cuda_runtime.h>
#include <cuda_fp16.h>
#include <cstdint>

#define NMAX 50000
#define EMAX 800000
#define F 144

typedef unsigned long long ull;
typedef unsigned int uint;

// ---- scratch (no allocations allowed; __device__ globals) ----
__device__ int    g_deg[NMAX];
__device__ float  g_dinv[NMAX];
__device__ int    g_rowptr[NMAX + 1];
__device__ int    g_cursor[NMAX];
__device__ int2   g_edge[EMAX];                  // {col, valbits}
__device__ int    g_bsum[128];
__device__ int    g_boff[128];
__device__ float4 g_tx1[(size_t)NMAX * 36];      // Tx1 fp32 (GEMM operand)
__device__ float4 g_tx2[(size_t)NMAX * 36];      // z = L*Tx1 fp32 (GEMM operand)
__device__ uint2  g_xh [(size_t)NMAX * 36];      // x   fp16 (gather copy)
__device__ uint2  g_t1h[(size_t)NMAX * 36];      // Tx1 fp16 (gather copy)
__device__ float  g_wcat[432 * 144];             // [W0-W2 ; W1 ; 2*W2]

// register-only fp16x2 -> float2 (no address-of, cannot spill)
__device__ __forceinline__ float2 h2tof2(uint h) {
    float2 r;
    asm("{\n\t"
        ".reg .b16 lo, hi;\n\t"
        "mov.b32 {lo, hi}, %2;\n\t"
        "cvt.f32.f16 %0, lo;\n\t"
        "cvt.f32.f16 %1, hi;\n\t"
        "}" : "=f"(r.x), "=f"(r.y) : "r"(h));
    return r;
}
// register-only float,float -> fp16x2 (hi goes to high half)
__device__ __forceinline__ uint f2toh2(float lo, float hi) {
    uint u;
    asm("cvt.rn.f16x2.f32 %0, %1, %2;" : "=r"(u) : "f"(hi), "f"(lo));
    return u;
}

// ---------------------------------------------------------------------------
// 1) prep: zero deg, build concatenated weights, x -> fp16
// ---------------------------------------------------------------------------
__global__ void prep_kernel(const float* __restrict__ x,
                            const float* __restrict__ wgt, int n) {
    int i = blockIdx.x * blockDim.x + threadIdx.x;
    if (i < n) g_deg[i] = 0;
    if (i < 432 * 144) {
        int k = i / 144, j = i % 144;
        float v;
        if (k < 144)      v = wgt[i] - wgt[(288 + k) * 144 + j];
        else if (k < 288) v = wgt[i];
        else              v = 2.0f * wgt[i];
        g_wcat[i] = v;
    }
    int nh = n * 72;   // one fp16x2 word per thread
    if (i < nh) {
        float2 f = *reinterpret_cast<const float2*>(x + 2 * i);
        reinterpret_cast<uint*>(g_xh)[i] = f2toh2(f.x, f.y);
    }
}

// ---------------------------------------------------------------------------
// 2) degree histogram (self-loops masked)
// ---------------------------------------------------------------------------
__global__ void hist4_kernel(const int* __restrict__ row, const int* __restrict__ col, int e) {
    int i = (blockIdx.x * blockDim.x + threadIdx.x) * 4;
    if (i + 4 <= e) {
        int4 r = *reinterpret_cast<const int4*>(row + i);
        int4 c = *reinterpret_cast<const int4*>(col + i);
        if (r.x != c.x) atomicAdd(&g_deg[r.x], 1);
        if (r.y != c.y) atomicAdd(&g_deg[r.y], 1);
        if (r.z != c.z) atomicAdd(&g_deg[r.z], 1);
        if (r.w != c.w) atomicAdd(&g_deg[r.w], 1);
    } else {
        for (; i < e; ++i) {
            int r = row[i];
            if (r != col[i]) atomicAdd(&g_deg[r], 1);
        }
    }
}

// ---------------------------------------------------------------------------
// 3) 3-kernel scan (proven): reduce, block-scan, local scan + offset
// ---------------------------------------------------------------------------
__global__ void scanA_kernel(int n) {
    __shared__ int sm[512];
    int t = threadIdx.x, i = blockIdx.x * 512 + t;
    sm[t] = (i < n) ? g_deg[i] : 0;
    __syncthreads();
    for (int off = 256; off > 0; off >>= 1) {
        if (t < off) sm[t] += sm[t + off];
        __syncthreads();
    }
    if (t == 0) g_bsum[blockIdx.x] = sm[0];
}

__global__ void scanB_kernel(int nb) {
    __shared__ int sm[128];
    int t = threadIdx.x;
    sm[t] = (t < nb) ? g_bsum[t] : 0;
    __syncthreads();
    for (int off = 1; off < 128; off <<= 1) {
        int v = (t >= off) ? sm[t - off] : 0;
        __syncthreads();
        sm[t] += v;
        __syncthreads();
    }
    if (t < nb) g_boff[t] = t ? sm[t - 1] : 0;
}

__global__ void scanC_kernel(int n) {
    __shared__ int sm[512];
    int t = threadIdx.x, b = blockIdx.x, i = b * 512 + t;
    int d = (i < n) ? g_deg[i] : 0;
    sm[t] = d;
    __syncthreads();
    for (int off = 1; off < 512; off <<= 1) {
        int v = (t >= off) ? sm[t - off] : 0;
        __syncthreads();
        sm[t] += v;
        __syncthreads();
    }
    if (i < n) {
        int excl = g_boff[b] + sm[t] - d;
        g_rowptr[i] = excl;
        g_cursor[i] = excl;
        g_dinv[i] = (d > 0) ? rsqrtf((float)d) : 0.0f;
        if (i == n - 1) g_rowptr[n] = excl + d;
    }
}

// ---------------------------------------------------------------------------
// 4) scatter edges into CSR (4 edges/thread)
// ---------------------------------------------------------------------------
__global__ void scatter4_kernel(const int* __restrict__ row, const int* __restrict__ col,
                                const float* __restrict__ w, int e) {
    int i = (blockIdx.x * blockDim.x + threadIdx.x) * 4;
    if (i + 4 <= e) {
        int4 r = *reinterpret_cast<const int4*>(row + i);
        int4 c = *reinterpret_cast<const int4*>(col + i);
        float4 ww = *reinterpret_cast<const float4*>(w + i);
        float dr0 = g_dinv[r.x], dc0 = g_dinv[c.x];
        float dr1 = g_dinv[r.y], dc1 = g_dinv[c.y];
        float dr2 = g_dinv[r.z], dc2 = g_dinv[c.z];
        float dr3 = g_dinv[r.w], dc3 = g_dinv[c.w];
        if (r.x != c.x) {
            int p = atomicAdd(&g_cursor[r.x], 1);
            g_edge[p] = make_int2(c.x, __float_as_int(-dr0 * ww.x * dc0));
        }
        if (r.y != c.y) {
            int p = atomicAdd(&g_cursor[r.y], 1);
            g_edge[p] = make_int2(c.y, __float_as_int(-dr1 * ww.y * dc1));
        }
        if (r.z != c.z) {
            int p = atomicAdd(&g_cursor[r.z], 1);
            g_edge[p] = make_int2(c.z, __float_as_int(-dr2 * ww.z * dc2));
        }
        if (r.w != c.w) {
            int p = atomicAdd(&g_cursor[r.w], 1);
            g_edge[p] = make_int2(c.w, __float_as_int(-dr3 * ww.w * dc3));
        }
    } else {
        for (; i < e; ++i) {
            int r = row[i], c = col[i];
            if (r != c) {
                int p = atomicAdd(&g_cursor[r], 1);
                g_edge[p] = make_int2(c, __float_as_int(-g_dinv[r] * w[i] * g_dinv[c]));
            }
        }
    }
}

// ---------------------------------------------------------------------------
// 5) SpMM v3: ONE WARP PER ROW (divergence-free), fp16 gathers, fp32 accum
//    lanes 0-31: uint2 features [0,128); lanes 0-3 also tail [128,144)
//    pass 0: tx1 = L @ x    pass 1: z = L @ tx1 (2x folded into wcat)
// ---------------------------------------------------------------------------
__device__ __forceinline__ void hacc(float4& acc, float w, uint2 u) {
    float2 a = h2tof2(u.x);
    float2 b = h2tof2(u.y);
    acc.x = fmaf(w, a.x, acc.x); acc.y = fmaf(w, a.y, acc.y);
    acc.z = fmaf(w, b.x, acc.z); acc.w = fmaf(w, b.y, acc.w);
}

__global__ __launch_bounds__(256) void spmm_kernel(int n, int pass) {
    int r = blockIdx.x * 8 + (threadIdx.x >> 5);
    if (r >= n) return;
    int lane = threadIdx.x & 31;
    bool tail = lane < 4;

    const uint2* __restrict__ src = pass ? g_t1h : g_xh;

    int s = g_rowptr[r];
    int e = g_rowptr[r + 1];

    float4 accA = make_float4(0.f, 0.f, 0.f, 0.f);
    float4 accB = make_float4(0.f, 0.f, 0.f, 0.f);
    const uint2 zz = make_uint2(0u, 0u);

    int i = s;
    for (; i + 4 <= e; i += 4) {
        int2 e0 = __ldg(&g_edge[i + 0]);
        int2 e1 = __ldg(&g_edge[i + 1]);
        int2 e2 = __ldg(&g_edge[i + 2]);
        int2 e3 = __ldg(&g_edge[i + 3]);
        const uint2* p0 = src + (size_t)e0.x * 36;
        const uint2* p1 = src + (size_t)e1.x * 36;
        const uint2* p2 = src + (size_t)e2.x * 36;
        const uint2* p3 = src + (size_t)e3.x * 36;
        uint2 a0 = __ldg(p0 + lane);
        uint2 a1 = __ldg(p1 + lane);
        uint2 a2 = __ldg(p2 + lane);
        uint2 a3 = __ldg(p3 + lane);
        uint2 b0 = tail ? __ldg(p0 + 32 + lane) : zz;
        uint2 b1 = tail ? __ldg(p1 + 32 + lane) : zz;
        uint2 b2 = tail ? __ldg(p2 + 32 + lane) : zz;
        uint2 b3 = tail ? __ldg(p3 + 32 + lane) : zz;
        float w0 = __int_as_float(e0.y), w1 = __int_as_float(e1.y);
        float w2 = __int_as_float(e2.y), w3 = __int_as_float(e3.y);
        hacc(accA, w0, a0); hacc(accB, w0, b0);
        hacc(accA, w1, a1); hacc(accB, w1, b1);
        hacc(accA, w2, a2); hacc(accB, w2, b2);
        hacc(accA, w3, a3); hacc(accB, w3, b3);
    }
    for (; i < e; ++i) {
        int2 ee = __ldg(&g_edge[i]);
        const uint2* p = src + (size_t)ee.x * 36;
        uint2 a = __ldg(p + lane);
        uint2 b = tail ? __ldg(p + 32 + lane) : zz;
        float w = __int_as_float(ee.y);
        hacc(accA, w, a); hacc(accB, w, b);
    }

    size_t o = (size_t)r * 36;
    if (pass) {
        g_tx2[o + lane] = accA;
        if (tail) g_tx2[o + 32 + lane] = accB;
    } else {
        g_tx1[o + lane] = accA;
        uint2 u;
        u.x = f2toh2(accA.x, accA.y);
        u.y = f2toh2(accA.z, accA.w);
        g_t1h[o + lane] = u;
        if (tail) {
            g_tx1[o + 32 + lane] = accB;
            uint2 v;
            v.x = f2toh2(accB.x, accB.y);
            v.y = f2toh2(accB.z, accB.w);
            g_t1h[o + 32 + lane] = v;
        }
    }
}

// ---------------------------------------------------------------------------
// 6) fused GEMM: out[N,144] = [x|tx1|z] @ g_wcat + bias
//    BM=128, BK=24, 384 threads, 4x12 micro-tile, packed f32x2 FMA
// ---------------------------------------------------------------------------
#define BM 128
#define GT 384

__device__ __forceinline__ ull fdup(float v) {
    unsigned u = __float_as_uint(v);
    return (ull)u | ((ull)u << 32);
}
__device__ __forceinline__ void ffma2(ull& d, ull a, ull b) {
    asm("fma.rn.f32x2 %0, %1, %2, %0;" : "+l"(d) : "l"(a), "l"(b));
}

__global__ __launch_bounds__(GT) void gemm_kernel(const float* __restrict__ x,
                                                  const float* __restrict__ bias,
                                                  float* __restrict__ out, int n) {
    __shared__ __align__(16) ull   As[24 * 130];
    __shared__ __align__(16) float Bs[24 * 148];

    int tid = threadIdx.x;
    int m0 = blockIdx.x * BM;
    int cg = tid % 12;
    int rg = tid / 12;
    int colS = 12 * cg + ((cg >= 8) ? 2 : 0);
    int colG = 12 * cg;

    int qa0 = tid % 6,         ma0 = tid / 6;
    int qa1 = (GT + tid) % 6,  ma1 = (GT + tid) / 6;
    int physb[9];
#pragma unroll
    for (int p = 0; p < 9; ++p) {
        int idx = p * GT + tid;
        int j = idx % 144, kk = idx / 144;
        physb[p] = kk * 148 + j + ((j >= 96) ? 2 : 0);
    }

    ull acc[4][6];
#pragma unroll
    for (int r = 0; r < 4; ++r)
#pragma unroll
        for (int p = 0; p < 6; ++p) acc[r][p] = 0ull;

    const float* t1 = (const float*)g_tx1;
    const float* t2 = (const float*)g_tx2;

    float4 av0, av1;
    float bv[9];

    {   // prefetch kt = 0
        int gm0 = m0 + ma0, gm1 = m0 + ma1;
        av0 = (gm0 < n) ? *reinterpret_cast<const float4*>(x + (size_t)gm0 * 144 + 4 * qa0)
                        : make_float4(0.f, 0.f, 0.f, 0.f);
        av1 = (gm1 < n) ? *reinterpret_cast<const float4*>(x + (size_t)gm1 * 144 + 4 * qa1)
                        : make_float4(0.f, 0.f, 0.f, 0.f);
#pragma unroll
        for (int p = 0; p < 9; ++p) bv[p] = g_wcat[p * GT + tid];
    }

    for (int kt = 0; kt < 18; ++kt) {
        As[(4 * qa0 + 0) * 130 + ma0] = fdup(av0.x);
        As[(4 * qa0 + 1) * 130 + ma0] = fdup(av0.y);
        As[(4 * qa0 + 2) * 130 + ma0] = fdup(av0.z);
        As[(4 * qa0 + 3) * 130 + ma0] = fdup(av0.w);
        As[(4 * qa1 + 0) * 130 + ma1] = fdup(av1.x);
        As[(4 * qa1 + 1) * 130 + ma1] = fdup(av1.y);
        As[(4 * qa1 + 2) * 130 + ma1] = fdup(av1.z);
        As[(4 * qa1 + 3) * 130 + ma1] = fdup(av1.w);
#pragma unroll
        for (int p = 0; p < 9; ++p) Bs[physb[p]] = bv[p];
        __syncthreads();

        if (kt < 17) {
            int kn = kt + 1;
            int s = kn / 6;
            int kl = (kn % 6) * 24;
            const float* A = (s == 0) ? x : ((s == 1) ? t1 : t2);
            int gm0 = m0 + ma0, gm1 = m0 + ma1;
            av0 = (gm0 < n) ? *reinterpret_cast<const float4*>(A + (size_t)gm0 * 144 + kl + 4 * qa0)
                            : make_float4(0.f, 0.f, 0.f, 0.f);
            av1 = (gm1 < n) ? *reinterpret_cast<const float4*>(A + (size_t)gm1 * 144 + kl + 4 * qa1)
                            : make_float4(0.f, 0.f, 0.f, 0.f);
            const float* Wt = g_wcat + (size_t)kn * 3456;
#pragma unroll
            for (int p = 0; p < 9; ++p) bv[p] = __ldg(&Wt[p * GT + tid]);
        }

#pragma unroll
        for (int kk = 0; kk < 24; ++kk) {
            const ull* ar = &As[kk * 130 + rg * 4];
            ulonglong2 A01 = *reinterpret_cast<const ulonglong2*>(ar);
            ulonglong2 A23 = *reinterpret_cast<const ulonglong2*>(ar + 2);
            ull a0 = A01.x, a1 = A01.y, a2 = A23.x, a3 = A23.y;
            const float* bp = &Bs[kk * 148 + colS];
            ull b0 = *reinterpret_cast<const ull*>(bp);
            ull b1 = *reinterpret_cast<const ull*>(bp + 2);
            ull b2 = *reinterpret_cast<const ull*>(bp + 4);
            ull b3 = *reinterpret_cast<const ull*>(bp + 6);
            ull b4 = *reinterpret_cast<const ull*>(bp + 8);
            ull b5 = *reinterpret_cast<const ull*>(bp + 10);
            ffma2(acc[0][0], a0, b0); ffma2(acc[0][1], a0, b1); ffma2(acc[0][2], a0, b2);
            ffma2(acc[0][3], a0, b3); ffma2(acc[0][4], a0, b4); ffma2(acc[0][5], a0, b5);
            ffma2(acc[1][0], a1, b0); ffma2(acc[1][1], a1, b1); ffma2(acc[1][2], a1, b2);
            ffma2(acc[1][3], a1, b3); ffma2(acc[1][4], a1, b4); ffma2(acc[1][5], a1, b5);
            ffma2(acc[2][0], a2, b0); ffma2(acc[2][1], a2, b1); ffma2(acc[2][2], a2, b2);
            ffma2(acc[2][3], a2, b3); ffma2(acc[2][4], a2, b4); ffma2(acc[2][5], a2, b5);
            ffma2(acc[3][0], a3, b0); ffma2(acc[3][1], a3, b1); ffma2(acc[3][2], a3, b2);
            ffma2(acc[3][3], a3, b3); ffma2(acc[3][4], a3, b4); ffma2(acc[3][5], a3, b5);
        }
        __syncthreads();
    }

    float bl[12];
#pragma unroll
    for (int t = 0; t < 12; ++t) bl[t] = __ldg(&bias[colG + t]);

#pragma unroll
    for (int r = 0; r < 4; ++r) {
        int gm = m0 + rg * 4 + r;
        if (gm < n) {
            float* o = out + (size_t)gm * 144 + colG;
#pragma unroll
            for (int q = 0; q < 3; ++q) {
                ull p0 = acc[r][2 * q], p1 = acc[r][2 * q + 1];
                float4 v;
                v.x = __uint_as_float((unsigned)(p0 & 0xffffffffu)) + bl[4 * q + 0];
                v.y = __uint_as_float((unsigned)(p0 >> 32))         + bl[4 * q + 1];
                v.z = __uint_as_float((unsigned)(p1 & 0xffffffffu)) + bl[4 * q + 2];
                v.w = __uint_as_float((unsigned)(p1 >> 32))         + bl[4 * q + 3];
                *reinterpret_cast<float4*>(o + 4 * q) = v;
            }
        }
    }
}

// ---------------------------------------------------------------------------
// launcher
// ---------------------------------------------------------------------------
extern "C" void kernel_launch(void* const* d_in, const int* in_sizes, int n_in,
                              void* d_out, int out_size) {
    const float* x    = (const float*)d_in[0];   // [N, 144]
    const int*   ei   = (const int*)d_in[1];     // [2, E]
    const float* ew   = (const float*)d_in[2];   // [E]
    const float* wgt  = (const float*)d_in[3];   // [3, 144, 144]
    const float* bias = (const float*)d_in[4];   // [144]
    float* out = (float*)d_out;

    int n = in_sizes[0] / F;
    int e = in_sizes[2];
    const int* row = ei;
    const int* col = ei + e;
    int nb = (n + 511) / 512;

    prep_kernel<<<(n * 72 + 255) / 256, 256>>>(x, wgt, n);
    hist4_kernel<<<((e + 3) / 4 + 255) / 256, 256>>>(row, col, e);
    scanA_kernel<<<nb, 512>>>(n);
    scanB_kernel<<<1, 128>>>(nb);
    scanC_kernel<<<nb, 512>>>(n);
    scatter4_kernel<<<((e + 3) / 4 + 255) / 256, 256>>>(row, col, ew, e);

    spmm_kernel<<<(n + 7) / 8, 256>>>(n, 0);   // tx1 = L x    (warp per row)
    spmm_kernel<<<(n + 7) / 8, 256>>>(n, 1);   // z   = L tx1  (warp per row)

    gemm_kernel<<<(n + BM - 1) / BM, GT>>>(x, bias, out, n);
}

// round 14
// speedup vs baseline: 2.0369x; 2.0369x over previous
#include <cuda_runtime.h>
#include <cuda_fp16.h>
#include <cstdint>

#define NMAX 50000
#define EMAX 800000
#define F 144

typedef unsigned long long ull;
typedef unsigned int uint;

// ---- scratch (no allocations allowed; __device__ globals) ----
__device__ int    g_deg[NMAX];
__device__ float  g_dinv[NMAX];
__device__ int    g_rowptr[NMAX + 1];
__device__ int    g_cursor[NMAX];
__device__ int2   g_edge[EMAX];                  // {col, valbits}
__device__ int    g_bsum[128];
__device__ int    g_boff[128];
__device__ uint2  g_xh [(size_t)NMAX * 36];      // x   fp16  [N][72 words]
__device__ uint2  g_t1h[(size_t)NMAX * 36];      // Tx1 fp16
__device__ uint2  g_t2h[(size_t)NMAX * 36];      // z = L*Tx1 fp16
__device__ uint   g_wkn[432 * 72];               // B[k][n] fp16 words (folded weights)

// register-only fp16x2 -> float2
__device__ __forceinline__ float2 h2tof2(uint h) {
    float2 r;
    asm("{\n\t"
        ".reg .b16 lo, hi;\n\t"
        "mov.b32 {lo, hi}, %2;\n\t"
        "cvt.f32.f16 %0, lo;\n\t"
        "cvt.f32.f16 %1, hi;\n\t"
        "}" : "=f"(r.x), "=f"(r.y) : "r"(h));
    return r;
}
// register-only (lo,hi) -> fp16x2 word
__device__ __forceinline__ uint f2toh2(float lo, float hi) {
    uint u;
    asm("cvt.rn.f16x2.f32 %0, %1, %2;" : "=r"(u) : "f"(hi), "f"(lo));
    return u;
}
__device__ __forceinline__ uint smem_u32(const void* p) {
    uint a;
    asm("{ .reg .u64 t; cvta.to.shared.u64 t, %1; cvt.u32.u64 %0, t; }" : "=r"(a) : "l"(p));
    return a;
}

// ---------------------------------------------------------------------------
// 1) prep: zero deg, x -> fp16, build B[k][n] fp16 = folded weights
//    B = [W0-W2 ; W1 ; 2*W2]  (out = x@(W0-W2) + Tx1@W1 + (L Tx1)@(2W2) + bias)
// ---------------------------------------------------------------------------
__global__ void prep_kernel(const float* __restrict__ x,
                            const float* __restrict__ wgt, int n) {
    int i = blockIdx.x * blockDim.x + threadIdx.x;
    if (i < n) g_deg[i] = 0;
    if (i < 432 * 72) {
        int k = i / 72, w = i % 72;
        float f[2];
#pragma unroll
        for (int h = 0; h < 2; ++h) {
            int nn = 2 * w + h;
            float base = wgt[k * 144 + nn];
            if (k < 144)      f[h] = base - wgt[(288 + k) * 144 + nn];
            else if (k < 288) f[h] = base;
            else              f[h] = 2.0f * base;
        }
        g_wkn[i] = f2toh2(f[0], f[1]);
    }
    int nh = n * 72;
    if (i < nh) {
        float2 f = *reinterpret_cast<const float2*>(x + 2 * i);
        reinterpret_cast<uint*>(g_xh)[i] = f2toh2(f.x, f.y);
    }
}

// ---------------------------------------------------------------------------
// 2) degree histogram
// ---------------------------------------------------------------------------
__global__ void hist4_kernel(const int* __restrict__ row, const int* __restrict__ col, int e) {
    int i = (blockIdx.x * blockDim.x + threadIdx.x) * 4;
    if (i + 4 <= e) {
        int4 r = *reinterpret_cast<const int4*>(row + i);
        int4 c = *reinterpret_cast<const int4*>(col + i);
        if (r.x != c.x) atomicAdd(&g_deg[r.x], 1);
        if (r.y != c.y) atomicAdd(&g_deg[r.y], 1);
        if (r.z != c.z) atomicAdd(&g_deg[r.z], 1);
        if (r.w != c.w) atomicAdd(&g_deg[r.w], 1);
    } else {
        for (; i < e; ++i) {
            int r = row[i];
            if (r != col[i]) atomicAdd(&g_deg[r], 1);
        }
    }
}

// ---------------------------------------------------------------------------
// 3) 3-kernel scan
// ---------------------------------------------------------------------------
__global__ void scanA_kernel(int n) {
    __shared__ int sm[512];
    int t = threadIdx.x, i = blockIdx.x * 512 + t;
    sm[t] = (i < n) ? g_deg[i] : 0;
    __syncthreads();
    for (int off = 256; off > 0; off >>= 1) {
        if (t < off) sm[t] += sm[t + off];
        __syncthreads();
    }
    if (t == 0) g_bsum[blockIdx.x] = sm[0];
}
__global__ void scanB_kernel(int nb) {
    __shared__ int sm[128];
    int t = threadIdx.x;
    sm[t] = (t < nb) ? g_bsum[t] : 0;
    __syncthreads();
    for (int off = 1; off < 128; off <<= 1) {
        int v = (t >= off) ? sm[t - off] : 0;
        __syncthreads();
        sm[t] += v;
        __syncthreads();
    }
    if (t < nb) g_boff[t] = t ? sm[t - 1] : 0;
}
__global__ void scanC_kernel(int n) {
    __shared__ int sm[512];
    int t = threadIdx.x, b = blockIdx.x, i = b * 512 + t;
    int d = (i < n) ? g_deg[i] : 0;
    sm[t] = d;
    __syncthreads();
    for (int off = 1; off < 512; off <<= 1) {
        int v = (t >= off) ? sm[t - off] : 0;
        __syncthreads();
        sm[t] += v;
        __syncthreads();
    }
    if (i < n) {
        int excl = g_boff[b] + sm[t] - d;
        g_rowptr[i] = excl;
        g_cursor[i] = excl;
        g_dinv[i] = (d > 0) ? rsqrtf((float)d) : 0.0f;
        if (i == n - 1) g_rowptr[n] = excl + d;
    }
}

// ---------------------------------------------------------------------------
// 4) scatter edges into CSR
// ---------------------------------------------------------------------------
__global__ void scatter4_kernel(const int* __restrict__ row, const int* __restrict__ col,
                                const float* __restrict__ w, int e) {
    int i = (blockIdx.x * blockDim.x + threadIdx.x) * 4;
    if (i + 4 <= e) {
        int4 r = *reinterpret_cast<const int4*>(row + i);
        int4 c = *reinterpret_cast<const int4*>(col + i);
        float4 ww = *reinterpret_cast<const float4*>(w + i);
        float dr0 = g_dinv[r.x], dc0 = g_dinv[c.x];
        float dr1 = g_dinv[r.y], dc1 = g_dinv[c.y];
        float dr2 = g_dinv[r.z], dc2 = g_dinv[c.z];
        float dr3 = g_dinv[r.w], dc3 = g_dinv[c.w];
        if (r.x != c.x) {
            int p = atomicAdd(&g_cursor[r.x], 1);
            g_edge[p] = make_int2(c.x, __float_as_int(-dr0 * ww.x * dc0));
        }
        if (r.y != c.y) {
            int p = atomicAdd(&g_cursor[r.y], 1);
            g_edge[p] = make_int2(c.y, __float_as_int(-dr1 * ww.y * dc1));
        }
        if (r.z != c.z) {
            int p = atomicAdd(&g_cursor[r.z], 1);
            g_edge[p] = make_int2(c.z, __float_as_int(-dr2 * ww.z * dc2));
        }
        if (r.w != c.w) {
            int p = atomicAdd(&g_cursor[r.w], 1);
            g_edge[p] = make_int2(c.w, __float_as_int(-dr3 * ww.w * dc3));
        }
    } else {
        for (; i < e; ++i) {
            int r = row[i], c = col[i];
            if (r != c) {
                int p = atomicAdd(&g_cursor[r], 1);
                g_edge[p] = make_int2(c, __float_as_int(-g_dinv[r] * w[i] * g_dinv[c]));
            }
        }
    }
}

// ---------------------------------------------------------------------------
// 5) SpMM (R9-proven layout), fp16 gather, fp32 accum, fp16 outputs
// ---------------------------------------------------------------------------
__device__ __forceinline__ void hacc(float4& acc, float w, uint2 u) {
    float2 a = h2tof2(u.x);
    float2 b = h2tof2(u.y);
    acc.x = fmaf(w, a.x, acc.x); acc.y = fmaf(w, a.y, acc.y);
    acc.z = fmaf(w, b.x, acc.z); acc.w = fmaf(w, b.y, acc.w);
}

__global__ void spmm_kernel(int n, int pass) {
    int r = blockIdx.x * 8 + threadIdx.y;
    if (r >= n) return;
    int lane = threadIdx.x;  // 0..35

    const uint2* __restrict__ src = pass ? g_t1h : g_xh;

    int s = g_rowptr[r];
    int e = g_rowptr[r + 1];

    float4 acc = make_float4(0.f, 0.f, 0.f, 0.f);
    int i = s;
    for (; i + 4 <= e; i += 4) {
        int2 e0 = __ldg(&g_edge[i + 0]);
        int2 e1 = __ldg(&g_edge[i + 1]);
        int2 e2 = __ldg(&g_edge[i + 2]);
        int2 e3 = __ldg(&g_edge[i + 3]);
        uint2 u0 = __ldg(&src[(size_t)e0.x * 36 + lane]);
        uint2 u1 = __ldg(&src[(size_t)e1.x * 36 + lane]);
        uint2 u2 = __ldg(&src[(size_t)e2.x * 36 + lane]);
        uint2 u3 = __ldg(&src[(size_t)e3.x * 36 + lane]);
        hacc(acc, __int_as_float(e0.y), u0);
        hacc(acc, __int_as_float(e1.y), u1);
        hacc(acc, __int_as_float(e2.y), u2);
        hacc(acc, __int_as_float(e3.y), u3);
    }
    for (; i < e; ++i) {
        int2 ee = __ldg(&g_edge[i]);
        uint2 u = __ldg(&src[(size_t)ee.x * 36 + lane]);
        hacc(acc, __int_as_float(ee.y), u);
    }

    size_t o = (size_t)r * 36 + lane;
    uint2 u;
    u.x = f2toh2(acc.x, acc.y);
    u.y = f2toh2(acc.z, acc.w);
    if (pass) g_t2h[o] = u;
    else      g_t1h[o] = u;
}

// ---------------------------------------------------------------------------
// 6) HMMA GEMM: out[N,144] = [x|Tx1|z]_f16 @ B_f16 + bias (fp32 accumulate)
//    mma.sync.m16n8k16 + ldmatrix. 256 thr, tile 128x144, K = 9 chunks x 48.
//    8 warps = 4(m) x 2(n); warp tile 32x72 = 2 m16 x 9 n8.
//    A smem [128][56] halves (112B stride), B smem [48][152] (304B stride).
// ---------------------------------------------------------------------------
__device__ __forceinline__ void ldsm_x4(uint* r, uint addr) {
    asm volatile("ldmatrix.sync.aligned.m8n8.x4.shared.b16 {%0,%1,%2,%3}, [%4];"
                 : "=r"(r[0]), "=r"(r[1]), "=r"(r[2]), "=r"(r[3]) : "r"(addr));
}
__device__ __forceinline__ void ldsm_x2t(uint& r0, uint& r1, uint addr) {
    asm volatile("ldmatrix.sync.aligned.m8n8.x2.trans.shared.b16 {%0,%1}, [%2];"
                 : "=r"(r0), "=r"(r1) : "r"(addr));
}
__device__ __forceinline__ void mma16816(float* c, const uint* a, uint b0, uint b1) {
    asm volatile(
        "mma.sync.aligned.m16n8k16.row.col.f32.f16.f16.f32 "
        "{%0,%1,%2,%3}, {%4,%5,%6,%7}, {%8,%9}, {%0,%1,%2,%3};"
        : "+f"(c[0]), "+f"(c[1]), "+f"(c[2]), "+f"(c[3])
        : "r"(a[0]), "r"(a[1]), "r"(a[2]), "r"(a[3]), "r"(b0), "r"(b1));
}

__global__ __launch_bounds__(256) void gemm_hmma_kernel(const float* __restrict__ bias,
                                                        float* __restrict__ out, int n) {
    __shared__ __align__(16) __half sA[128 * 56];
    __shared__ __align__(16) __half sB[48 * 152];

    int tid = threadIdx.x;
    int lane = tid & 31;
    int wid = tid >> 5;
    int wm = wid & 3;             // 0..3 -> rows wm*32
    int wn = wid >> 2;            // 0..1 -> cols wn*72
    int m0 = blockIdx.x * 128;

    uint aBase = smem_u32(sA);
    uint bBase = smem_u32(sB);
    uint* sAu = (uint*)sA;
    uint* sBu = (uint*)sB;

    // ldmatrix lane geometry (shared by A and B)
    int lrow = (lane & 7) + (lane & 8);      // 0..15
    int lcb  = (lane >> 4) << 3;             // 0 or 8

    float acc0[9][4], acc1[9][4];
#pragma unroll
    for (int ni = 0; ni < 9; ++ni)
#pragma unroll
        for (int q = 0; q < 4; ++q) { acc0[ni][q] = 0.f; acc1[ni][q] = 0.f; }

    const uint* srcs[3] = { (const uint*)g_xh, (const uint*)g_t1h, (const uint*)g_t2h };

    uint pa[12], pb[14];
    // prefetch chunk 0
    {
        const uint* src = srcs[0];
#pragma unroll
        for (int p = 0; p < 12; ++p) {
            int idx = p * 256 + tid;
            int r = idx / 24, w = idx % 24;
            int gm = m0 + r;
            pa[p] = (gm < n) ? __ldg(&src[(size_t)gm * 72 + w]) : 0u;
        }
#pragma unroll
        for (int p = 0; p < 14; ++p) {
            int idx = p * 256 + tid;
            pb[p] = (idx < 3456) ? __ldg(&g_wkn[idx]) : 0u;
        }
    }

    for (int kc = 0; kc < 9; ++kc) {
        // store staged chunk to smem
#pragma unroll
        for (int p = 0; p < 12; ++p) {
            int idx = p * 256 + tid;
            int r = idx / 24, w = idx % 24;
            sAu[r * 28 + w] = pa[p];
        }
#pragma unroll
        for (int p = 0; p < 14; ++p) {
            int idx = p * 256 + tid;
            if (idx < 3456) {
                int kl = idx / 72, w = idx % 72;
                sBu[kl * 76 + w] = pb[p];
            }
        }
        __syncthreads();

        // prefetch next chunk
        if (kc < 8) {
            int kn = kc + 1;
            const uint* src = srcs[kn / 3];
            int off = (kn % 3) * 24;
#pragma unroll
            for (int p = 0; p < 12; ++p) {
                int idx = p * 256 + tid;
                int r = idx / 24, w = idx % 24;
                int gm = m0 + r;
                pa[p] = (gm < n) ? __ldg(&src[(size_t)gm * 72 + off + w]) : 0u;
            }
            const uint* wsrc = g_wkn + kn * 48 * 72;
#pragma unroll
            for (int p = 0; p < 14; ++p) {
                int idx = p * 256 + tid;
                pb[p] = (idx < 3456) ? __ldg(&wsrc[idx]) : 0u;
            }
        }

        // compute: 3 k16 steps
#pragma unroll
        for (int ks = 0; ks < 3; ++ks) {
            int kl = ks * 16;
            uint a0[4], a1[4];
            ldsm_x4(a0, aBase + (uint)(((wm * 32 +      lrow) * 56 + kl + lcb) * 2));
            ldsm_x4(a1, aBase + (uint)(((wm * 32 + 16 + lrow) * 56 + kl + lcb) * 2));
#pragma unroll
            for (int ni = 0; ni < 9; ++ni) {
                uint b0, b1;
                ldsm_x2t(b0, b1, bBase + (uint)(((kl + lrow) * 152 + wn * 72 + ni * 8) * 2));
                mma16816(acc0[ni], a0, b0, b1);
                mma16816(acc1[ni], a1, b0, b1);
            }
        }
        __syncthreads();
    }

    // epilogue: C fragment -> gmem with bias
    int grp = lane >> 2;
    int cq  = (lane & 3) * 2;
#pragma unroll
    for (int mi = 0; mi < 2; ++mi) {
        float (*acc)[4] = mi ? acc1 : acc0;
        int rbase = m0 + wm * 32 + mi * 16 + grp;
#pragma unroll
        for (int ni = 0; ni < 9; ++ni) {
            int col = wn * 72 + ni * 8 + cq;
            float bv0 = __ldg(&bias[col]);
            float bv1 = __ldg(&bias[col + 1]);
            if (rbase < n) {
                float2 v = make_float2(acc[ni][0] + bv0, acc[ni][1] + bv1);
                *reinterpret_cast<float2*>(out + (size_t)rbase * 144 + col) = v;
            }
            if (rbase + 8 < n) {
                float2 v = make_float2(acc[ni][2] + bv0, acc[ni][3] + bv1);
                *reinterpret_cast<float2*>(out + (size_t)(rbase + 8) * 144 + col) = v;
            }
        }
    }
}

// ---------------------------------------------------------------------------
// launcher
// ---------------------------------------------------------------------------
extern "C" void kernel_launch(void* const* d_in, const int* in_sizes, int n_in,
                              void* d_out, int out_size) {
    const float* x    = (const float*)d_in[0];   // [N, 144]
    const int*   ei   = (const int*)d_in[1];     // [2, E]
    const float* ew   = (const float*)d_in[2];   // [E]
    const float* wgt  = (const float*)d_in[3];   // [3, 144, 144]
    const float* bias = (const float*)d_in[4];   // [144]
    float* out = (float*)d_out;

    int n = in_sizes[0] / F;
    int e = in_sizes[2];
    const int* row = ei;
    const int* col = ei + e;
    int nb = (n + 511) / 512;

    prep_kernel<<<(n * 72 + 255) / 256, 256>>>(x, wgt, n);
    hist4_kernel<<<((e + 3) / 4 + 255) / 256, 256>>>(row, col, e);
    scanA_kernel<<<nb, 512>>>(n);
    scanB_kernel<<<1, 128>>>(nb);
    scanC_kernel<<<nb, 512>>>(n);
    scatter4_kernel<<<((e + 3) / 4 + 255) / 256, 256>>>(row, col, ew, e);

    dim3 sb(36, 8);
    spmm_kernel<<<(n + 7) / 8, sb>>>(n, 0);   // Tx1 = L x
    spmm_kernel<<<(n + 7) / 8, sb>>>(n, 1);   // z   = L Tx1  (2x folded into B)

    gemm_hmma_kernel<<<(n + 127) / 128, 256>>>(bias, out, n);
}

// round 16
// speedup vs baseline: 2.1244x; 1.0429x over previous
#include <cuda_runtime.h>
#include <cuda_fp16.h>
#include <cstdint>

#define NMAX 50000
#define EMAX 800000
#define F 144

typedef unsigned long long ull;
typedef unsigned int uint;

// ---- scratch (no allocations allowed; __device__ globals) ----
__device__ int    g_deg[NMAX];
__device__ float  g_dinv[NMAX];
__device__ int    g_rowptr[NMAX + 1];
__device__ int    g_cursor[NMAX];
__device__ int2   g_edge[EMAX];                  // {col, valbits}
__device__ int    g_bsum[128];
__device__ uint2  g_xh [(size_t)NMAX * 36];      // x   fp16  [N][72 words]
__device__ uint2  g_t1h[(size_t)NMAX * 36];      // Tx1 fp16
__device__ uint2  g_t2h[(size_t)NMAX * 36];      // z = L*Tx1 fp16
__device__ uint   g_wkn[432 * 72];               // B[k][n] fp16 words (folded weights)

// register-only fp16x2 -> float2
__device__ __forceinline__ float2 h2tof2(uint h) {
    float2 r;
    asm("{\n\t"
        ".reg .b16 lo, hi;\n\t"
        "mov.b32 {lo, hi}, %2;\n\t"
        "cvt.f32.f16 %0, lo;\n\t"
        "cvt.f32.f16 %1, hi;\n\t"
        "}" : "=f"(r.x), "=f"(r.y) : "r"(h));
    return r;
}
__device__ __forceinline__ uint f2toh2(float lo, float hi) {
    uint u;
    asm("cvt.rn.f16x2.f32 %0, %1, %2;" : "=r"(u) : "f"(hi), "f"(lo));
    return u;
}
__device__ __forceinline__ uint smem_u32(const void* p) {
    uint a;
    asm("{ .reg .u64 t; cvta.to.shared.u64 t, %1; cvt.u32.u64 %0, t; }" : "=r"(a) : "l"(p));
    return a;
}

// ---------------------------------------------------------------------------
// 1) prep: zero deg, x -> fp16, build folded weights B[k][n] fp16
// ---------------------------------------------------------------------------
__global__ void prep_kernel(const float* __restrict__ x,
                            const float* __restrict__ wgt, int n) {
    int i = blockIdx.x * blockDim.x + threadIdx.x;
    if (i < n) g_deg[i] = 0;
    if (i < 432 * 72) {
        int k = i / 72, w = i % 72;
        float f[2];
#pragma unroll
        for (int h = 0; h < 2; ++h) {
            int nn = 2 * w + h;
            float base = wgt[k * 144 + nn];
            if (k < 144)      f[h] = base - wgt[(288 + k) * 144 + nn];
            else if (k < 288) f[h] = base;
            else              f[h] = 2.0f * base;
        }
        g_wkn[i] = f2toh2(f[0], f[1]);
    }
    int nh = n * 72;
    if (i < nh) {
        float2 f = *reinterpret_cast<const float2*>(x + 2 * i);
        reinterpret_cast<uint*>(g_xh)[i] = f2toh2(f.x, f.y);
    }
}

// ---------------------------------------------------------------------------
// 2) degree histogram, 8 edges/thread
// ---------------------------------------------------------------------------
__global__ void hist8_kernel(const int* __restrict__ row, const int* __restrict__ col, int e) {
    int i = (blockIdx.x * blockDim.x + threadIdx.x) * 8;
    if (i + 8 <= e) {
#pragma unroll
        for (int q = 0; q < 2; ++q) {
            int4 r = *reinterpret_cast<const int4*>(row + i + 4 * q);
            int4 c = *reinterpret_cast<const int4*>(col + i + 4 * q);
            if (r.x != c.x) atomicAdd(&g_deg[r.x], 1);
            if (r.y != c.y) atomicAdd(&g_deg[r.y], 1);
            if (r.z != c.z) atomicAdd(&g_deg[r.z], 1);
            if (r.w != c.w) atomicAdd(&g_deg[r.w], 1);
        }
    } else {
        for (; i < e; ++i) {
            int r = row[i];
            if (r != col[i]) atomicAdd(&g_deg[r], 1);
        }
    }
}

// ---------------------------------------------------------------------------
// 3) scan: A = per-block reduce; C = self-computed base + local scan
// ---------------------------------------------------------------------------
__global__ void scanA_kernel(int n) {
    __shared__ int sm[512];
    int t = threadIdx.x, i = blockIdx.x * 512 + t;
    sm[t] = (i < n) ? g_deg[i] : 0;
    __syncthreads();
    for (int off = 256; off > 0; off >>= 1) {
        if (t < off) sm[t] += sm[t + off];
        __syncthreads();
    }
    if (t == 0) g_bsum[blockIdx.x] = sm[0];
}

__global__ void scanC_kernel(int n, int nb) {
    __shared__ int sm[512];
    __shared__ int bs[128];
    int t = threadIdx.x, b = blockIdx.x, i = b * 512 + t;
    int d = (i < n) ? g_deg[i] : 0;
    sm[t] = d;
    if (t < 128) bs[t] = (t < nb && t < b) ? g_bsum[t] : 0;
    __syncthreads();
    // reduce bs -> base (sum of block sums before b)
    for (int off = 64; off > 0; off >>= 1) {
        if (t < off) bs[t] += bs[t + off];
        __syncthreads();
    }
    int base = bs[0];
    // local inclusive scan of degrees
    for (int off = 1; off < 512; off <<= 1) {
        int v = (t >= off) ? sm[t - off] : 0;
        __syncthreads();
        sm[t] += v;
        __syncthreads();
    }
    if (i < n) {
        int excl = base + sm[t] - d;
        g_rowptr[i] = excl;
        g_cursor[i] = excl;
        g_dinv[i] = (d > 0) ? rsqrtf((float)d) : 0.0f;
        if (i == n - 1) g_rowptr[n] = excl + d;
    }
}

// ---------------------------------------------------------------------------
// 4) scatter edges into CSR, 8 edges/thread
// ---------------------------------------------------------------------------
__global__ void scatter8_kernel(const int* __restrict__ row, const int* __restrict__ col,
                                const float* __restrict__ w, int e) {
    int i = (blockIdx.x * blockDim.x + threadIdx.x) * 8;
    if (i + 8 <= e) {
#pragma unroll
        for (int q = 0; q < 2; ++q) {
            int4 r = *reinterpret_cast<const int4*>(row + i + 4 * q);
            int4 c = *reinterpret_cast<const int4*>(col + i + 4 * q);
            float4 ww = *reinterpret_cast<const float4*>(w + i + 4 * q);
            float dr0 = g_dinv[r.x], dc0 = g_dinv[c.x];
            float dr1 = g_dinv[r.y], dc1 = g_dinv[c.y];
            float dr2 = g_dinv[r.z], dc2 = g_dinv[c.z];
            float dr3 = g_dinv[r.w], dc3 = g_dinv[c.w];
            if (r.x != c.x) {
                int p = atomicAdd(&g_cursor[r.x], 1);
                g_edge[p] = make_int2(c.x, __float_as_int(-dr0 * ww.x * dc0));
            }
            if (r.y != c.y) {
                int p = atomicAdd(&g_cursor[r.y], 1);
                g_edge[p] = make_int2(c.y, __float_as_int(-dr1 * ww.y * dc1));
            }
            if (r.z != c.z) {
                int p = atomicAdd(&g_cursor[r.z], 1);
                g_edge[p] = make_int2(c.z, __float_as_int(-dr2 * ww.z * dc2));
            }
            if (r.w != c.w) {
                int p = atomicAdd(&g_cursor[r.w], 1);
                g_edge[p] = make_int2(c.w, __float_as_int(-dr3 * ww.w * dc3));
            }
        }
    } else {
        for (; i < e; ++i) {
            int r = row[i], c = col[i];
            if (r != c) {
                int p = atomicAdd(&g_cursor[r], 1);
                g_edge[p] = make_int2(c, __float_as_int(-g_dinv[r] * w[i] * g_dinv[c]));
            }
        }
    }
}

// ---------------------------------------------------------------------------
// 5) SpMM (R9-proven layout), fp16 gather, fp32 accum, fp16 outputs
// ---------------------------------------------------------------------------
__device__ __forceinline__ void hacc(float4& acc, float w, uint2 u) {
    float2 a = h2tof2(u.x);
    float2 b = h2tof2(u.y);
    acc.x = fmaf(w, a.x, acc.x); acc.y = fmaf(w, a.y, acc.y);
    acc.z = fmaf(w, b.x, acc.z); acc.w = fmaf(w, b.y, acc.w);
}

__global__ void spmm_kernel(int n, int pass) {
    int r = blockIdx.x * 8 + threadIdx.y;
    if (r >= n) return;
    int lane = threadIdx.x;  // 0..35

    const uint2* __restrict__ src = pass ? g_t1h : g_xh;

    int s = g_rowptr[r];
    int e = g_rowptr[r + 1];

    float4 acc = make_float4(0.f, 0.f, 0.f, 0.f);
    int i = s;
    for (; i + 4 <= e; i += 4) {
        int2 e0 = __ldg(&g_edge[i + 0]);
        int2 e1 = __ldg(&g_edge[i + 1]);
        int2 e2 = __ldg(&g_edge[i + 2]);
        int2 e3 = __ldg(&g_edge[i + 3]);
        uint2 u0 = __ldg(&src[(size_t)e0.x * 36 + lane]);
        uint2 u1 = __ldg(&src[(size_t)e1.x * 36 + lane]);
        uint2 u2 = __ldg(&src[(size_t)e2.x * 36 + lane]);
        uint2 u3 = __ldg(&src[(size_t)e3.x * 36 + lane]);
        hacc(acc, __int_as_float(e0.y), u0);
        hacc(acc, __int_as_float(e1.y), u1);
        hacc(acc, __int_as_float(e2.y), u2);
        hacc(acc, __int_as_float(e3.y), u3);
    }
    for (; i < e; ++i) {
        int2 ee = __ldg(&g_edge[i]);
        uint2 u = __ldg(&src[(size_t)ee.x * 36 + lane]);
        hacc(acc, __int_as_float(ee.y), u);
    }

    size_t o = (size_t)r * 36 + lane;
    uint2 u;
    u.x = f2toh2(acc.x, acc.y);
    u.y = f2toh2(acc.z, acc.w);
    if (pass) g_t2h[o] = u;
    else      g_t1h[o] = u;
}

// ---------------------------------------------------------------------------
// 6) HMMA GEMM: out[N,144] = [x|Tx1|z]_f16 @ B_f16 + bias (fp32 accumulate)
//    BM=192: 384 thr, 12 warps = 6(m) x 2(n); warp tile 32x72 = 2 m16 x 9 n8.
//    K = 9 chunks x 48. A smem [192][56] halves, B smem [48][152].
// ---------------------------------------------------------------------------
#define GBM 192
#define GGT 384

__device__ __forceinline__ void ldsm_x4(uint* r, uint addr) {
    asm volatile("ldmatrix.sync.aligned.m8n8.x4.shared.b16 {%0,%1,%2,%3}, [%4];"
                 : "=r"(r[0]), "=r"(r[1]), "=r"(r[2]), "=r"(r[3]) : "r"(addr));
}
__device__ __forceinline__ void ldsm_x2t(uint& r0, uint& r1, uint addr) {
    asm volatile("ldmatrix.sync.aligned.m8n8.x2.trans.shared.b16 {%0,%1}, [%2];"
                 : "=r"(r0), "=r"(r1) : "r"(addr));
}
__device__ __forceinline__ void mma16816(float* c, const uint* a, uint b0, uint b1) {
    asm volatile(
        "mma.sync.aligned.m16n8k16.row.col.f32.f16.f16.f32 "
        "{%0,%1,%2,%3}, {%4,%5,%6,%7}, {%8,%9}, {%0,%1,%2,%3};"
        : "+f"(c[0]), "+f"(c[1]), "+f"(c[2]), "+f"(c[3])
        : "r"(a[0]), "r"(a[1]), "r"(a[2]), "r"(a[3]), "r"(b0), "r"(b1));
}

__global__ __launch_bounds__(GGT) void gemm_hmma_kernel(const float* __restrict__ bias,
                                                        float* __restrict__ out, int n) {
    __shared__ __align__(16) __half sA[GBM * 56];
    __shared__ __align__(16) __half sB[48 * 152];

    int tid = threadIdx.x;
    int lane = tid & 31;
    int wid = tid >> 5;
    int wm = wid >> 1;            // 0..5 -> rows wm*32
    int wn = wid & 1;             // 0..1 -> cols wn*72
    int m0 = blockIdx.x * GBM;

    uint aBase = smem_u32(sA);
    uint bBase = smem_u32(sB);
    uint* sAu = (uint*)sA;
    uint* sBu = (uint*)sB;

    int lrow = (lane & 7) + (lane & 8);      // 0..15
    int lcb  = (lane >> 4) << 3;             // 0 or 8

    float acc0[9][4], acc1[9][4];
#pragma unroll
    for (int ni = 0; ni < 9; ++ni)
#pragma unroll
        for (int q = 0; q < 4; ++q) { acc0[ni][q] = 0.f; acc1[ni][q] = 0.f; }

    const uint* srcs[3] = { (const uint*)g_xh, (const uint*)g_t1h, (const uint*)g_t2h };

    uint pa[12], pb[9];
    // prefetch chunk 0  (A: 192x24 words = 4608 = 12*384; B: 3456 = 9*384)
    {
        const uint* src = srcs[0];
#pragma unroll
        for (int p = 0; p < 12; ++p) {
            int idx = p * GGT + tid;
            int r = idx / 24, w = idx % 24;
            int gm = m0 + r;
            pa[p] = (gm < n) ? __ldg(&src[(size_t)gm * 72 + w]) : 0u;
        }
#pragma unroll
        for (int p = 0; p < 9; ++p) pb[p] = __ldg(&g_wkn[p * GGT + tid]);
    }

    for (int kc = 0; kc < 9; ++kc) {
        // store staged chunk to smem
#pragma unroll
        for (int p = 0; p < 12; ++p) {
            int idx = p * GGT + tid;
            int r = idx / 24, w = idx % 24;
            sAu[r * 28 + w] = pa[p];
        }
#pragma unroll
        for (int p = 0; p < 9; ++p) {
            int idx = p * GGT + tid;
            int kl = idx / 72, w = idx % 72;
            sBu[kl * 76 + w] = pb[p];
        }
        __syncthreads();

        // prefetch next chunk
        if (kc < 8) {
            int kn = kc + 1;
            const uint* src = srcs[kn / 3];
            int off = (kn % 3) * 24;
#pragma unroll
            for (int p = 0; p < 12; ++p) {
                int idx = p * GGT + tid;
                int r = idx / 24, w = idx % 24;
                int gm = m0 + r;
                pa[p] = (gm < n) ? __ldg(&src[(size_t)gm * 72 + off + w]) : 0u;
            }
            const uint* wsrc = g_wkn + kn * 48 * 72;
#pragma unroll
            for (int p = 0; p < 9; ++p) pb[p] = __ldg(&wsrc[p * GGT + tid]);
        }

        // compute: 3 k16 steps
#pragma unroll
        for (int ks = 0; ks < 3; ++ks) {
            int kl = ks * 16;
            uint a0[4], a1[4];
            ldsm_x4(a0, aBase + (uint)(((wm * 32 +      lrow) * 56 + kl + lcb) * 2));
            ldsm_x4(a1, aBase + (uint)(((wm * 32 + 16 + lrow) * 56 + kl + lcb) * 2));
#pragma unroll
            for (int ni = 0; ni < 9; ++ni) {
                uint b0, b1;
                ldsm_x2t(b0, b1, bBase + (uint)(((kl + lrow) * 152 + wn * 72 + ni * 8) * 2));
                mma16816(acc0[ni], a0, b0, b1);
                mma16816(acc1[ni], a1, b0, b1);
            }
        }
        __syncthreads();
    }

    // epilogue: C fragment -> gmem with bias
    int grp = lane >> 2;
    int cq  = (lane & 3) * 2;
#pragma unroll
    for (int mi = 0; mi < 2; ++mi) {
        float (*acc)[4] = mi ? acc1 : acc0;
        int rbase = m0 + wm * 32 + mi * 16 + grp;
#pragma unroll
        for (int ni = 0; ni < 9; ++ni) {
            int col = wn * 72 + ni * 8 + cq;
            float bv0 = __ldg(&bias[col]);
            float bv1 = __ldg(&bias[col + 1]);
            if (rbase < n) {
                float2 v = make_float2(acc[ni][0] + bv0, acc[ni][1] + bv1);
                *reinterpret_cast<float2*>(out + (size_t)rbase * 144 + col) = v;
            }
            if (rbase + 8 < n) {
                float2 v = make_float2(acc[ni][2] + bv0, acc[ni][3] + bv1);
                *reinterpret_cast<float2*>(out + (size_t)(rbase + 8) * 144 + col) = v;
            }
        }
    }
}

// ---------------------------------------------------------------------------
// launcher
// ---------------------------------------------------------------------------
extern "C" void kernel_launch(void* const* d_in, const int* in_sizes, int n_in,
                              void* d_out, int out_size) {
    const float* x    = (const float*)d_in[0];   // [N, 144]
    const int*   ei   = (const int*)d_in[1];     // [2, E]
    const float* ew   = (const float*)d_in[2];   // [E]
    const float* wgt  = (const float*)d_in[3];   // [3, 144, 144]
    const float* bias = (const float*)d_in[4];   // [144]
    float* out = (float*)d_out;

    int n = in_sizes[0] / F;
    int e = in_sizes[2];
    const int* row = ei;
    const int* col = ei + e;
    int nb = (n + 511) / 512;

    prep_kernel<<<(n * 72 + 255) / 256, 256>>>(x, wgt, n);
    hist8_kernel<<<((e + 7) / 8 + 255) / 256, 256>>>(row, col, e);
    scanA_kernel<<<nb, 512>>>(n);
    scanC_kernel<<<nb, 512>>>(n, nb);
    scatter8_kernel<<<((e + 7) / 8 + 255) / 256, 256>>>(row, col, ew, e);

    dim3 sb(36, 8);
    spmm_kernel<<<(n + 7) / 8, sb>>>(n, 0);   // Tx1 = L x
    spmm_kernel<<<(n + 7) / 8, sb>>>(n, 1);   // z   = L Tx1  (2x folded into B)

    gemm_hmma_kernel<<<(n + GBM - 1) / GBM, GGT>>>(bias, out, n);
}

// round 17
// speedup vs baseline: 2.3316x; 1.0975x over previous
#include <cuda_runtime.h>
#include <cuda_fp16.h>
#include <cstdint>

#define NMAX 50000
#define EMAX 800000
#define F 144

typedef unsigned long long ull;
typedef unsigned int uint;

// ---- scratch (no allocations allowed; __device__ globals) ----
__device__ int    g_deg[NMAX];
__device__ float  g_dinv[NMAX];
__device__ int    g_rowptr[NMAX + 1];
__device__ int    g_cursor[NMAX];
__device__ int2   g_edge[EMAX];                  // {col, valbits}
__device__ int    g_bsum[128];
__device__ uint4  g_xh [(size_t)NMAX * 18];      // x   fp16  [N][18 uint4]
__device__ uint4  g_t1h[(size_t)NMAX * 18];      // Tx1 fp16
__device__ uint4  g_t2h[(size_t)NMAX * 18];      // z = L*Tx1 fp16
__device__ uint   g_wkn[432 * 72];               // B[k][n] fp16 words (folded weights)

// register-only fp16x2 -> float2
__device__ __forceinline__ float2 h2tof2(uint h) {
    float2 r;
    asm("{\n\t"
        ".reg .b16 lo, hi;\n\t"
        "mov.b32 {lo, hi}, %2;\n\t"
        "cvt.f32.f16 %0, lo;\n\t"
        "cvt.f32.f16 %1, hi;\n\t"
        "}" : "=f"(r.x), "=f"(r.y) : "r"(h));
    return r;
}
__device__ __forceinline__ uint f2toh2(float lo, float hi) {
    uint u;
    asm("cvt.rn.f16x2.f32 %0, %1, %2;" : "=r"(u) : "f"(hi), "f"(lo));
    return u;
}
__device__ __forceinline__ uint smem_u32(const void* p) {
    uint a;
    asm("{ .reg .u64 t; cvta.to.shared.u64 t, %1; cvt.u32.u64 %0, t; }" : "=r"(a) : "l"(p));
    return a;
}

// ---------------------------------------------------------------------------
// 1) prep: zero deg, x -> fp16, build folded weights B[k][n] fp16
// ---------------------------------------------------------------------------
__global__ void prep_kernel(const float* __restrict__ x,
                            const float* __restrict__ wgt, int n) {
    int i = blockIdx.x * blockDim.x + threadIdx.x;
    if (i < n) g_deg[i] = 0;
    if (i < 432 * 72) {
        int k = i / 72, w = i % 72;
        float f[2];
#pragma unroll
        for (int h = 0; h < 2; ++h) {
            int nn = 2 * w + h;
            float base = wgt[k * 144 + nn];
            if (k < 144)      f[h] = base - wgt[(288 + k) * 144 + nn];
            else if (k < 288) f[h] = base;
            else              f[h] = 2.0f * base;
        }
        g_wkn[i] = f2toh2(f[0], f[1]);
    }
    int nh = n * 72;
    if (i < nh) {
        float2 f = *reinterpret_cast<const float2*>(x + 2 * i);
        reinterpret_cast<uint*>(g_xh)[i] = f2toh2(f.x, f.y);
    }
}

// ---------------------------------------------------------------------------
// 2) degree histogram, 8 edges/thread
// ---------------------------------------------------------------------------
__global__ void hist8_kernel(const int* __restrict__ row, const int* __restrict__ col, int e) {
    int i = (blockIdx.x * blockDim.x + threadIdx.x) * 8;
    if (i + 8 <= e) {
#pragma unroll
        for (int q = 0; q < 2; ++q) {
            int4 r = *reinterpret_cast<const int4*>(row + i + 4 * q);
            int4 c = *reinterpret_cast<const int4*>(col + i + 4 * q);
            if (r.x != c.x) atomicAdd(&g_deg[r.x], 1);
            if (r.y != c.y) atomicAdd(&g_deg[r.y], 1);
            if (r.z != c.z) atomicAdd(&g_deg[r.z], 1);
            if (r.w != c.w) atomicAdd(&g_deg[r.w], 1);
        }
    } else {
        for (; i < e; ++i) {
            int r = row[i];
            if (r != col[i]) atomicAdd(&g_deg[r], 1);
        }
    }
}

// ---------------------------------------------------------------------------
// 3) scan: A = per-block reduce; C = shuffle scan + self-computed base
// ---------------------------------------------------------------------------
__global__ void scanA_kernel(int n) {
    __shared__ int sm[512];
    int t = threadIdx.x, i = blockIdx.x * 512 + t;
    sm[t] = (i < n) ? g_deg[i] : 0;
    __syncthreads();
    for (int off = 256; off > 0; off >>= 1) {
        if (t < off) sm[t] += sm[t + off];
        __syncthreads();
    }
    if (t == 0) g_bsum[blockIdx.x] = sm[0];
}

__global__ void scanC_kernel(int n, int nb) {
    __shared__ int ws[16];
    __shared__ int bs[128];
    int t = threadIdx.x, b = blockIdx.x, i = b * 512 + t;
    int lane = t & 31, w = t >> 5;
    int d = (i < n) ? g_deg[i] : 0;
    if (t < 128) bs[t] = (t < nb && t < b) ? g_bsum[t] : 0;

    // warp inclusive scan of degrees
    int v = d;
#pragma unroll
    for (int off = 1; off < 32; off <<= 1) {
        int u = __shfl_up_sync(0xffffffffu, v, off);
        if (lane >= off) v += u;
    }
    if (lane == 31) ws[w] = v;
    __syncthreads();

    if (t < 64) bs[t] += bs[t + 64];
    __syncthreads();

    if (t < 32) {
        int s = bs[t] + bs[t + 32];
#pragma unroll
        for (int off = 16; off; off >>= 1) s += __shfl_down_sync(0xffffffffu, s, off);
        if (t == 0) bs[0] = s;
    }
    if (w == 2 && lane < 16) {   // warp 2: inclusive scan of the 16 warp sums
        int s = ws[lane];
#pragma unroll
        for (int off = 1; off < 16; off <<= 1) {
            int u = __shfl_up_sync(0x0000ffffu, s, off);
            if (lane >= off) s += u;
        }
        ws[lane] = s;
    }
    __syncthreads();

    int base = bs[0] + ((w > 0) ? ws[w - 1] : 0);
    if (i < n) {
        int excl = base + v - d;
        g_rowptr[i] = excl;
        g_cursor[i] = excl;
        g_dinv[i] = (d > 0) ? rsqrtf((float)d) : 0.0f;
        if (i == n - 1) g_rowptr[n] = excl + d;
    }
}

// ---------------------------------------------------------------------------
// 4) scatter edges into CSR, 8 edges/thread
// ---------------------------------------------------------------------------
__global__ void scatter8_kernel(const int* __restrict__ row, const int* __restrict__ col,
                                const float* __restrict__ w, int e) {
    int i = (blockIdx.x * blockDim.x + threadIdx.x) * 8;
    if (i + 8 <= e) {
#pragma unroll
        for (int q = 0; q < 2; ++q) {
            int4 r = *reinterpret_cast<const int4*>(row + i + 4 * q);
            int4 c = *reinterpret_cast<const int4*>(col + i + 4 * q);
            float4 ww = *reinterpret_cast<const float4*>(w + i + 4 * q);
            float dr0 = g_dinv[r.x], dc0 = g_dinv[c.x];
            float dr1 = g_dinv[r.y], dc1 = g_dinv[c.y];
            float dr2 = g_dinv[r.z], dc2 = g_dinv[c.z];
            float dr3 = g_dinv[r.w], dc3 = g_dinv[c.w];
            if (r.x != c.x) {
                int p = atomicAdd(&g_cursor[r.x], 1);
                g_edge[p] = make_int2(c.x, __float_as_int(-dr0 * ww.x * dc0));
            }
            if (r.y != c.y) {
                int p = atomicAdd(&g_cursor[r.y], 1);
                g_edge[p] = make_int2(c.y, __float_as_int(-dr1 * ww.y * dc1));
            }
            if (r.z != c.z) {
                int p = atomicAdd(&g_cursor[r.z], 1);
                g_edge[p] = make_int2(c.z, __float_as_int(-dr2 * ww.z * dc2));
            }
            if (r.w != c.w) {
                int p = atomicAdd(&g_cursor[r.w], 1);
                g_edge[p] = make_int2(c.w, __float_as_int(-dr3 * ww.w * dc3));
            }
        }
    } else {
        for (; i < e; ++i) {
            int r = row[i], c = col[i];
            if (r != c) {
                int p = atomicAdd(&g_cursor[r], 1);
                g_edge[p] = make_int2(c, __float_as_int(-g_dinv[r] * w[i] * g_dinv[c]));
            }
        }
    }
}

// ---------------------------------------------------------------------------
// 5) SpMM: (18,16) block, one uint4 (16B) gather per lane per edge.
//    fp16 gather, fp32 accum, fp16 outputs. 18 lanes x 16B = 288B row exact.
// ---------------------------------------------------------------------------
__device__ __forceinline__ void hacc4(float* acc, float w, uint4 u) {
    float2 a = h2tof2(u.x);
    float2 b = h2tof2(u.y);
    float2 c = h2tof2(u.z);
    float2 d = h2tof2(u.w);
    acc[0] = fmaf(w, a.x, acc[0]); acc[1] = fmaf(w, a.y, acc[1]);
    acc[2] = fmaf(w, b.x, acc[2]); acc[3] = fmaf(w, b.y, acc[3]);
    acc[4] = fmaf(w, c.x, acc[4]); acc[5] = fmaf(w, c.y, acc[5]);
    acc[6] = fmaf(w, d.x, acc[6]); acc[7] = fmaf(w, d.y, acc[7]);
}

__global__ void spmm_kernel(int n, int pass) {
    int r = blockIdx.x * 16 + threadIdx.y;
    if (r >= n) return;
    int lane = threadIdx.x;  // 0..17

    const uint4* __restrict__ src = pass ? g_t1h : g_xh;

    int s = g_rowptr[r];
    int e = g_rowptr[r + 1];

    float acc[8];
#pragma unroll
    for (int q = 0; q < 8; ++q) acc[q] = 0.f;

    int i = s;
    for (; i + 4 <= e; i += 4) {
        int2 e0 = __ldg(&g_edge[i + 0]);
        int2 e1 = __ldg(&g_edge[i + 1]);
        int2 e2 = __ldg(&g_edge[i + 2]);
        int2 e3 = __ldg(&g_edge[i + 3]);
        uint4 u0 = __ldg(&src[(size_t)e0.x * 18 + lane]);
        uint4 u1 = __ldg(&src[(size_t)e1.x * 18 + lane]);
        uint4 u2 = __ldg(&src[(size_t)e2.x * 18 + lane]);
        uint4 u3 = __ldg(&src[(size_t)e3.x * 18 + lane]);
        hacc4(acc, __int_as_float(e0.y), u0);
        hacc4(acc, __int_as_float(e1.y), u1);
        hacc4(acc, __int_as_float(e2.y), u2);
        hacc4(acc, __int_as_float(e3.y), u3);
    }
    for (; i < e; ++i) {
        int2 ee = __ldg(&g_edge[i]);
        uint4 u = __ldg(&src[(size_t)ee.x * 18 + lane]);
        hacc4(acc, __int_as_float(ee.y), u);
    }

    uint4 o;
    o.x = f2toh2(acc[0], acc[1]);
    o.y = f2toh2(acc[2], acc[3]);
    o.z = f2toh2(acc[4], acc[5]);
    o.w = f2toh2(acc[6], acc[7]);
    size_t oi = (size_t)r * 18 + lane;
    if (pass) g_t2h[oi] = o;
    else      g_t1h[oi] = o;
}

// ---------------------------------------------------------------------------
// 6) HMMA GEMM: out[N,144] = [x|Tx1|z]_f16 @ B_f16 + bias (fp32 accumulate)
//    BM=192: 384 thr, 12 warps = 6(m) x 2(n); warp tile 32x72 = 2 m16 x 9 n8.
//    K = 9 chunks x 48. B fragments via ldmatrix.x4.trans (pairs of n8).
// ---------------------------------------------------------------------------
#define GBM 192
#define GGT 384

__device__ __forceinline__ void ldsm_x4(uint* r, uint addr) {
    asm volatile("ldmatrix.sync.aligned.m8n8.x4.shared.b16 {%0,%1,%2,%3}, [%4];"
                 : "=r"(r[0]), "=r"(r[1]), "=r"(r[2]), "=r"(r[3]) : "r"(addr));
}
__device__ __forceinline__ void ldsm_x4t(uint* r, uint addr) {
    asm volatile("ldmatrix.sync.aligned.m8n8.x4.trans.shared.b16 {%0,%1,%2,%3}, [%4];"
                 : "=r"(r[0]), "=r"(r[1]), "=r"(r[2]), "=r"(r[3]) : "r"(addr));
}
__device__ __forceinline__ void ldsm_x2t(uint& r0, uint& r1, uint addr) {
    asm volatile("ldmatrix.sync.aligned.m8n8.x2.trans.shared.b16 {%0,%1}, [%2];"
                 : "=r"(r0), "=r"(r1) : "r"(addr));
}
__device__ __forceinline__ void mma16816(float* c, const uint* a, uint b0, uint b1) {
    asm volatile(
        "mma.sync.aligned.m16n8k16.row.col.f32.f16.f16.f32 "
        "{%0,%1,%2,%3}, {%4,%5,%6,%7}, {%8,%9}, {%0,%1,%2,%3};"
        : "+f"(c[0]), "+f"(c[1]), "+f"(c[2]), "+f"(c[3])
        : "r"(a[0]), "r"(a[1]), "r"(a[2]), "r"(a[3]), "r"(b0), "r"(b1));
}

__global__ __launch_bounds__(GGT) void gemm_hmma_kernel(const float* __restrict__ bias,
                                                        float* __restrict__ out, int n) {
    __shared__ __align__(16) __half sA[GBM * 56];
    __shared__ __align__(16) __half sB[48 * 152];

    int tid = threadIdx.x;
    int lane = tid & 31;
    int wid = tid >> 5;
    int wm = wid >> 1;            // 0..5 -> rows wm*32
    int wn = wid & 1;             // 0..1 -> cols wn*72
    int m0 = blockIdx.x * GBM;

    uint aBase = smem_u32(sA);
    uint bBase = smem_u32(sB);
    uint* sAu = (uint*)sA;
    uint* sBu = (uint*)sB;

    int lrow = (lane & 7) + (lane & 8);      // 0..15 (pattern repeats for lanes 16-31)
    int lcb  = (lane >> 4) << 3;             // 0 or 8
    int bc8  = (lane >> 4) << 3;             // x4t: lanes 16-31 take n+8 columns

    float acc0[9][4], acc1[9][4];
#pragma unroll
    for (int ni = 0; ni < 9; ++ni)
#pragma unroll
        for (int q = 0; q < 4; ++q) { acc0[ni][q] = 0.f; acc1[ni][q] = 0.f; }

    const uint* srcs[3] = { (const uint*)g_xh, (const uint*)g_t1h, (const uint*)g_t2h };

    uint pa[12], pb[9];
    // prefetch chunk 0  (A: 192x24 words = 4608 = 12*384; B: 3456 = 9*384)
    {
        const uint* src = srcs[0];
#pragma unroll
        for (int p = 0; p < 12; ++p) {
            int idx = p * GGT + tid;
            int r = idx / 24, w = idx % 24;
            int gm = m0 + r;
            pa[p] = (gm < n) ? __ldg(&src[(size_t)gm * 72 + w]) : 0u;
        }
#pragma unroll
        for (int p = 0; p < 9; ++p) pb[p] = __ldg(&g_wkn[p * GGT + tid]);
    }

    for (int kc = 0; kc < 9; ++kc) {
        // store staged chunk to smem
#pragma unroll
        for (int p = 0; p < 12; ++p) {
            int idx = p * GGT + tid;
            int r = idx / 24, w = idx % 24;
            sAu[r * 28 + w] = pa[p];
        }
#pragma unroll
        for (int p = 0; p < 9; ++p) {
            int idx = p * GGT + tid;
            int kl = idx / 72, w = idx % 72;
            sBu[kl * 76 + w] = pb[p];
        }
        __syncthreads();

        // prefetch next chunk
        if (kc < 8) {
            int kn = kc + 1;
            const uint* src = srcs[kn / 3];
            int off = (kn % 3) * 24;
#pragma unroll
            for (int p = 0; p < 12; ++p) {
                int idx = p * GGT + tid;
                int r = idx / 24, w = idx % 24;
                int gm = m0 + r;
                pa[p] = (gm < n) ? __ldg(&src[(size_t)gm * 72 + off + w]) : 0u;
            }
            const uint* wsrc = g_wkn + kn * 48 * 72;
#pragma unroll
            for (int p = 0; p < 9; ++p) pb[p] = __ldg(&wsrc[p * GGT + tid]);
        }

        // compute: 3 k16 steps; B loaded in n16 pairs via x4.trans
#pragma unroll
        for (int ks = 0; ks < 3; ++ks) {
            int kl = ks * 16;
            uint a0[4], a1[4];
            ldsm_x4(a0, aBase + (uint)(((wm * 32 +      lrow) * 56 + kl + lcb) * 2));
            ldsm_x4(a1, aBase + (uint)(((wm * 32 + 16 + lrow) * 56 + kl + lcb) * 2));
#pragma unroll
            for (int p = 0; p < 4; ++p) {
                uint br[4];
                ldsm_x4t(br, bBase + (uint)(((kl + lrow) * 152 + wn * 72 + p * 16 + bc8) * 2));
                mma16816(acc0[2 * p],     a0, br[0], br[1]);
                mma16816(acc1[2 * p],     a1, br[0], br[1]);
                mma16816(acc0[2 * p + 1], a0, br[2], br[3]);
                mma16816(acc1[2 * p + 1], a1, br[2], br[3]);
            }
            uint b0, b1;
            ldsm_x2t(b0, b1, bBase + (uint)(((kl + lrow) * 152 + wn * 72 + 64) * 2));
            mma16816(acc0[8], a0, b0, b1);
            mma16816(acc1[8], a1, b0, b1);
        }
        __syncthreads();
    }

    // epilogue: C fragment -> gmem with bias
    int grp = lane >> 2;
    int cq  = (lane & 3) * 2;
#pragma unroll
    for (int mi = 0; mi < 2; ++mi) {
        float (*acc)[4] = mi ? acc1 : acc0;
        int rbase = m0 + wm * 32 + mi * 16 + grp;
#pragma unroll
        for (int ni = 0; ni < 9; ++ni) {
            int col = wn * 72 + ni * 8 + cq;
            float bv0 = __ldg(&bias[col]);
            float bv1 = __ldg(&bias[col + 1]);
            if (rbase < n) {
                float2 v = make_float2(acc[ni][0] + bv0, acc[ni][1] + bv1);
                *reinterpret_cast<float2*>(out + (size_t)rbase * 144 + col) = v;
            }
            if (rbase + 8 < n) {
                float2 v = make_float2(acc[ni][2] + bv0, acc[ni][3] + bv1);
                *reinterpret_cast<float2*>(out + (size_t)(rbase + 8) * 144 + col) = v;
            }
        }
    }
}

// ---------------------------------------------------------------------------
// launcher
// ---------------------------------------------------------------------------
extern "C" void kernel_launch(void* const* d_in, const int* in_sizes, int n_in,
                              void* d_out, int out_size) {
    const float* x    = (const float*)d_in[0];   // [N, 144]
    const int*   ei   = (const int*)d_in[1];     // [2, E]
    const float* ew   = (const float*)d_in[2];   // [E]
    const float* wgt  = (const float*)d_in[3];   // [3, 144, 144]
    const float* bias = (const float*)d_in[4];   // [144]
    float* out = (float*)d_out;

    int n = in_sizes[0] / F;
    int e = in_sizes[2];
    const int* row = ei;
    const int* col = ei + e;
    int nb = (n + 511) / 512;

    prep_kernel<<<(n * 72 + 255) / 256, 256>>>(x, wgt, n);
    hist8_kernel<<<((e + 7) / 8 + 255) / 256, 256>>>(row, col, e);
    scanA_kernel<<<nb, 512>>>(n);
    scanC_kernel<<<nb, 512>>>(n, nb);
    scatter8_kernel<<<((e + 7) / 8 + 255) / 256, 256>>>(row, col, ew, e);

    dim3 sb(18, 16);
    spmm_kernel<<<(n + 15) / 16, sb>>>(n, 0);   // Tx1 = L x
    spmm_kernel<<<(n + 15) / 16, sb>>>(n, 1);   // z   = L Tx1  (2x folded into B)

    gemm_hmma_kernel<<<(n + GBM - 1) / GBM, GGT>>>(bias, out, n);
}